// round 2
// baseline (speedup 1.0000x reference)
#include <cuda_runtime.h>

#define NN  100000      // nodes
#define FIN 512         // input features
#define HID 16          // hidden
#define NC  40          // classes
#define MAXE 4000000    // capacity for edge scratch

// ---------------- device scratch (allocation-free rule: __device__ globals) ----
__device__ int   g_is64;
__device__ int   g_src[MAXE];
__device__ int   g_dst[MAXE];
__device__ float g_dinv[NN];                 // deg -> rsqrt(deg)
__device__ float g_h  [(size_t)NN * HID];    // h1, then y=relu(...)
__device__ float g_agg[(size_t)NN * HID];    // agg1, then agg2

// ---------------- helpers ------------------------------------------------------
__device__ __forceinline__ unsigned long long pack2(float v) {
    unsigned long long r;
    unsigned int u = __float_as_uint(v);
    asm("mov.b64 %0, {%1, %1};" : "=l"(r) : "r"(u));
    return r;
}
__device__ __forceinline__ unsigned long long ffma2(unsigned long long a,
                                                    unsigned long long b,
                                                    unsigned long long c) {
    unsigned long long d;
    asm("fma.rn.f32x2 %0, %1, %2, %3;" : "=l"(d) : "l"(a), "l"(b), "l"(c));
    return d;
}
__device__ __forceinline__ float2 unpack2(unsigned long long v) {
    unsigned int lo, hi;
    asm("mov.b64 {%0, %1}, %2;" : "=r"(lo), "=r"(hi) : "l"(v));
    return make_float2(__uint_as_float(lo), __uint_as_float(hi));
}
__device__ __forceinline__ void red4(float* p, float a, float b, float c, float d) {
    asm volatile("red.global.add.v4.f32 [%0], {%1,%2,%3,%4};"
                 :: "l"(p), "f"(a), "f"(b), "f"(c), "f"(d) : "memory");
}

// ---------------- index dtype detection + conversion ---------------------------
// If edge_index is int64, every odd 32-bit word (high half) is 0 (indices < 2^31).
// If int32, those words are random indices in [0, N) -> OR over 4096 of them != 0.
__global__ void detect_idx(const unsigned int* __restrict__ w, int E) {
    __shared__ unsigned int red[256];
    unsigned int acc = 0;
    int n = min(E, 4096);
    for (int i = threadIdx.x; i < n; i += 256) acc |= w[2 * i + 1];
    red[threadIdx.x] = acc;
    __syncthreads();
    for (int s = 128; s > 0; s >>= 1) {
        if (threadIdx.x < s) red[threadIdx.x] |= red[threadIdx.x + s];
        __syncthreads();
    }
    if (threadIdx.x == 0) g_is64 = (red[0] == 0u) ? 1 : 0;
}

__global__ __launch_bounds__(256) void convert_idx(const void* __restrict__ ei, int E) {
    int e = blockIdx.x * 256 + threadIdx.x;
    if (e >= E) return;
    if (g_is64) {
        const long long* p = (const long long*)ei;
        g_src[e] = (int)p[e];
        g_dst[e] = (int)p[e + E];
    } else {
        const int* p = (const int*)ei;
        g_src[e] = p[e];
        g_dst[e] = p[e + E];
    }
}

// ---------------- degree / dinv -------------------------------------------------
__global__ void deg_init(int N) {
    int i = blockIdx.x * 256 + threadIdx.x;
    if (i < N) g_dinv[i] = 1.0f;      // self-loop contributes 1 to in-degree
}
__global__ __launch_bounds__(256) void deg_count(int E) {
    int e = blockIdx.x * 256 + threadIdx.x;
    if (e < E) atomicAdd(&g_dinv[g_dst[e]], 1.0f);
}
__global__ void deg_finish(int N) {
    int i = blockIdx.x * 256 + threadIdx.x;
    if (i < N) g_dinv[i] = rsqrtf(g_dinv[i]);   // deg >= 1 always (self-loop)
}

// ---------------- GEMM1: h = x @ W1 ; agg = h * dinv^2 (self-loop term) --------
// 128 threads/block, 4 rows/thread => 512 rows/block. W1 (32KB) in smem.
// Packed f32x2 FMAs: 8 FFMA2 per (row, k).
__global__ __launch_bounds__(128) void gemm1(const float* __restrict__ x,
                                             const float* __restrict__ W1, int N) {
    __shared__ ulonglong2 Ws[FIN * 4];   // 512 rows x 16 floats = 32KB
    const ulonglong2* Wg = (const ulonglong2*)W1;
    for (int i = threadIdx.x; i < FIN * 4; i += 128) Ws[i] = Wg[i];
    __syncthreads();

    int base = blockIdx.x * 512 + threadIdx.x * 4;
    if (base >= N) return;

    unsigned long long acc[4][8];
#pragma unroll
    for (int r = 0; r < 4; r++)
#pragma unroll
        for (int p = 0; p < 8; p++) acc[r][p] = 0ull;

    int row[4];
    const float* xp[4];
#pragma unroll
    for (int r = 0; r < 4; r++) {
        row[r] = min(base + r, N - 1);
        xp[r] = x + (size_t)row[r] * FIN;
    }

    for (int k = 0; k < FIN; k += 4) {
        float xv[4][4];
#pragma unroll
        for (int r = 0; r < 4; r++)
            *(float4*)xv[r] = *(const float4*)(xp[r] + k);
#pragma unroll
        for (int j = 0; j < 4; j++) {
            ulonglong2 wa = Ws[(k + j) * 4 + 0];
            ulonglong2 wb = Ws[(k + j) * 4 + 1];
            ulonglong2 wc = Ws[(k + j) * 4 + 2];
            ulonglong2 wd = Ws[(k + j) * 4 + 3];
#pragma unroll
            for (int r = 0; r < 4; r++) {
                unsigned long long px = pack2(xv[r][j]);
                acc[r][0] = ffma2(px, wa.x, acc[r][0]);
                acc[r][1] = ffma2(px, wa.y, acc[r][1]);
                acc[r][2] = ffma2(px, wb.x, acc[r][2]);
                acc[r][3] = ffma2(px, wb.y, acc[r][3]);
                acc[r][4] = ffma2(px, wc.x, acc[r][4]);
                acc[r][5] = ffma2(px, wc.y, acc[r][5]);
                acc[r][6] = ffma2(px, wd.x, acc[r][6]);
                acc[r][7] = ffma2(px, wd.y, acc[r][7]);
            }
        }
    }

#pragma unroll
    for (int r = 0; r < 4; r++) {
        if (base + r >= N) break;
        int rw = row[r];
        float dv = g_dinv[rw];
        float sl = dv * dv;
        float* hp = g_h + (size_t)rw * HID;
        float* ap = g_agg + (size_t)rw * HID;
#pragma unroll
        for (int p = 0; p < 8; p++) {
            float2 v = unpack2(acc[r][p]);
            hp[2 * p + 0] = v.x;        hp[2 * p + 1] = v.y;
            ap[2 * p + 0] = v.x * sl;   ap[2 * p + 1] = v.y * sl;
        }
    }
}

// ---------------- edge aggregation: agg[dst] += h[src] * dinv[src]*dinv[dst] ----
__global__ __launch_bounds__(256) void edge_agg(int E) {
    int e = blockIdx.x * 256 + threadIdx.x;
    if (e >= E) return;
    int s = g_src[e];
    int d = g_dst[e];
    float nrm = g_dinv[s] * g_dinv[d];
    const float4* hp = (const float4*)(g_h + (size_t)s * HID);
    float4 v0 = hp[0], v1 = hp[1], v2 = hp[2], v3 = hp[3];
    float* out = g_agg + (size_t)d * HID;
    red4(out + 0,  v0.x * nrm, v0.y * nrm, v0.z * nrm, v0.w * nrm);
    red4(out + 4,  v1.x * nrm, v1.y * nrm, v1.z * nrm, v1.w * nrm);
    red4(out + 8,  v2.x * nrm, v2.y * nrm, v2.z * nrm, v2.w * nrm);
    red4(out + 12, v3.x * nrm, v3.y * nrm, v3.z * nrm, v3.w * nrm);
}

// ---------------- between layers: y = relu(agg + b1); h <- y; agg <- y*dinv^2 ---
__global__ __launch_bounds__(256) void relu_mid(const float* __restrict__ b1, int N) {
    int i = blockIdx.x * 256 + threadIdx.x;
    if (i >= N) return;
    float dv = g_dinv[i];
    float sl = dv * dv;
    float* hp = g_h + (size_t)i * HID;
    float* ap = g_agg + (size_t)i * HID;
#pragma unroll
    for (int c = 0; c < HID; c++) {
        float y = fmaxf(ap[c] + __ldg(&b1[c]), 0.0f);
        hp[c] = y;
        ap[c] = y * sl;
    }
}

// ---------------- final: logits = agg@W2 + b2 ; log_softmax ---------------------
__global__ __launch_bounds__(128) void final_k(const float* __restrict__ W2,
                                               const float* __restrict__ b2,
                                               float* __restrict__ out_lsm,
                                               float* __restrict__ out_logits,
                                               int N, int write_logits) {
    __shared__ float Ws[HID * NC];
    __shared__ float Bs[NC];
    for (int i = threadIdx.x; i < HID * NC; i += 128) Ws[i] = W2[i];
    if (threadIdx.x < NC) Bs[threadIdx.x] = b2[threadIdx.x];
    __syncthreads();

    int node = blockIdx.x * 128 + threadIdx.x;
    if (node >= N) return;

    const float* ap = g_agg + (size_t)node * HID;
    float a[HID];
#pragma unroll
    for (int j = 0; j < HID; j++) a[j] = ap[j];

    float z[NC];
#pragma unroll
    for (int c = 0; c < NC; c++) z[c] = Bs[c];
#pragma unroll
    for (int j = 0; j < HID; j++) {
        float aj = a[j];
#pragma unroll
        for (int c = 0; c < NC; c++) z[c] = fmaf(aj, Ws[j * NC + c], z[c]);
    }

    float m = z[0];
#pragma unroll
    for (int c = 1; c < NC; c++) m = fmaxf(m, z[c]);
    float s = 0.0f;
#pragma unroll
    for (int c = 0; c < NC; c++) s += __expf(z[c] - m);
    float lse = m + __logf(s);

    float* ol = out_lsm + (size_t)node * NC;
#pragma unroll
    for (int c = 0; c < NC; c++) ol[c] = z[c] - lse;
    if (write_logits) {
        float* og = out_logits + (size_t)node * NC;
#pragma unroll
        for (int c = 0; c < NC; c++) og[c] = z[c];
    }
}

// ---------------- launch --------------------------------------------------------
extern "C" void kernel_launch(void* const* d_in, const int* in_sizes, int n_in,
                              void* d_out, int out_size) {
    const float* x  = (const float*)d_in[0];
    const void*  ei = d_in[1];
    const float* W1 = (const float*)d_in[2];
    const float* b1 = (const float*)d_in[3];
    const float* W2 = (const float*)d_in[4];
    const float* b2 = (const float*)d_in[5];

    int E = in_sizes[1] / 2;
    if (E > MAXE) E = MAXE;
    int N = in_sizes[0] / FIN;
    if (N > NN) N = NN;

    float* out = (float*)d_out;
    int write_logits = (out_size >= 2 * N * NC) ? 1 : 0;
    float* out_lsm = out;
    float* out_logits = out + (size_t)N * NC;

    int nb_nodes = (N + 255) / 256;
    int nb_edges = (E + 255) / 256;

    detect_idx<<<1, 256>>>((const unsigned int*)ei, E);
    convert_idx<<<nb_edges, 256>>>(ei, E);
    deg_init<<<nb_nodes, 256>>>(N);
    deg_count<<<nb_edges, 256>>>(E);
    deg_finish<<<nb_nodes, 256>>>(N);
    gemm1<<<(N + 511) / 512, 128>>>(x, W1, N);
    edge_agg<<<nb_edges, 256>>>(E);
    relu_mid<<<nb_nodes, 256>>>(b1, N);
    edge_agg<<<nb_edges, 256>>>(E);
    final_k<<<(N + 127) / 128, 128>>>(W2, b2, out_lsm, out_logits, N, write_logits);
}

// round 4
// speedup vs baseline: 1.6277x; 1.6277x over previous
#include <cuda_runtime.h>

#define NN  100000      // nodes
#define FIN 512         // input features
#define HID 16          // hidden
#define NC  40          // classes
#define MAXE 4000000    // capacity for edge scratch
#define SCAN_B 512      // elems per scan block
#define NBLK ((NN + SCAN_B - 1) / SCAN_B)   // 196

// ---------------- device scratch --------------------------------------------
__device__ int   g_is64;
__device__ int   g_deg [NN];
__device__ int   g_scan[NN];
__device__ int   g_row [NN];
__device__ int   g_cur [NN];
__device__ int   g_bsum[256];
__device__ int   g_bpre[256];
__device__ float g_dinv[NN];
__device__ int   g_csr[MAXE];
__device__ float g_hs[(size_t)NN * HID];   // h1*dinv, later a2
__device__ float g_ys[(size_t)NN * HID];   // relu(out1)*dinv

// ---------------- index dtype detection -------------------------------------
__global__ void detect_idx(const unsigned int* __restrict__ w, int E) {
    __shared__ unsigned int red[256];
    unsigned int acc = 0;
    int n = min(E, 4096);
    for (int i = threadIdx.x; i < n; i += 256) acc |= w[2 * i + 1];
    red[threadIdx.x] = acc;
    __syncthreads();
    for (int s = 128; s > 0; s >>= 1) {
        if (threadIdx.x < s) red[threadIdx.x] |= red[threadIdx.x + s];
        __syncthreads();
    }
    if (threadIdx.x == 0) g_is64 = (red[0] == 0u) ? 1 : 0;
}

__device__ __forceinline__ void load_edge(const void* ei, int e, int E, int& s, int& d) {
    if (g_is64) {
        const long long* p = (const long long*)ei;
        s = (int)p[e];
        d = (int)p[e + E];
    } else {
        const int* p = (const int*)ei;
        s = p[e];
        d = p[e + E];
    }
}

// ---------------- degree count ----------------------------------------------
__global__ void zero_deg(int N) {
    int i = blockIdx.x * 256 + threadIdx.x;
    if (i < N) g_deg[i] = 0;
}
__global__ __launch_bounds__(256) void count_deg(const void* __restrict__ ei, int E) {
    int e = blockIdx.x * 256 + threadIdx.x;
    if (e >= E) return;
    int d;
    if (g_is64) {
        const long long* p = (const long long*)ei;
        d = (int)p[e + E];
    } else {
        const int* p = (const int*)ei;
        d = p[e + E];
    }
    atomicAdd(&g_deg[d], 1);
}

// ---------------- prefix scan (3 kernels) ------------------------------------
__global__ __launch_bounds__(SCAN_B) void scan1(int N) {
    __shared__ int sh[SCAN_B];
    int gid = blockIdx.x * SCAN_B + threadIdx.x;
    int v = (gid < N) ? g_deg[gid] : 0;
    sh[threadIdx.x] = v;
    __syncthreads();
    for (int off = 1; off < SCAN_B; off <<= 1) {
        int t = (threadIdx.x >= off) ? sh[threadIdx.x - off] : 0;
        __syncthreads();
        sh[threadIdx.x] += t;
        __syncthreads();
    }
    if (gid < N) g_scan[gid] = sh[threadIdx.x];
    if (threadIdx.x == SCAN_B - 1) g_bsum[blockIdx.x] = sh[SCAN_B - 1];
}
__global__ __launch_bounds__(256) void scan2(int nblk) {
    __shared__ int sh[256];
    int v = (threadIdx.x < nblk) ? g_bsum[threadIdx.x] : 0;
    sh[threadIdx.x] = v;
    __syncthreads();
    for (int off = 1; off < 256; off <<= 1) {
        int t = (threadIdx.x >= off) ? sh[threadIdx.x - off] : 0;
        __syncthreads();
        sh[threadIdx.x] += t;
        __syncthreads();
    }
    g_bpre[threadIdx.x] = sh[threadIdx.x] - v;   // exclusive
}
__global__ __launch_bounds__(SCAN_B) void scan3(int N) {
    int gid = blockIdx.x * SCAN_B + threadIdx.x;
    if (gid >= N) return;
    int dg = g_deg[gid];
    int rs = g_scan[gid] - dg + g_bpre[blockIdx.x];
    g_row[gid] = rs;
    g_cur[gid] = rs;
    g_dinv[gid] = rsqrtf((float)(dg + 1));   // +1 self-loop
}

// ---------------- CSR fill ----------------------------------------------------
__global__ __launch_bounds__(256) void csr_fill(const void* __restrict__ ei, int E) {
    int e = blockIdx.x * 256 + threadIdx.x;
    if (e >= E) return;
    int s, d;
    load_edge(ei, e, E, s, d);
    int pos = atomicAdd(&g_cur[d], 1);
    g_csr[pos] = s;
}

// ---------------- packed f32x2 helpers ---------------------------------------
__device__ __forceinline__ unsigned long long pack2(float v) {
    unsigned long long r;
    unsigned int u = __float_as_uint(v);
    asm("mov.b64 %0, {%1, %1};" : "=l"(r) : "r"(u));
    return r;
}
__device__ __forceinline__ unsigned long long ffma2(unsigned long long a,
                                                    unsigned long long b,
                                                    unsigned long long c) {
    unsigned long long d;
    asm("fma.rn.f32x2 %0, %1, %2, %3;" : "=l"(d) : "l"(a), "l"(b), "l"(c));
    return d;
}
__device__ __forceinline__ float2 unpack2(unsigned long long v) {
    unsigned int lo, hi;
    asm("mov.b64 {%0, %1}, %2;" : "=r"(lo), "=r"(hi) : "l"(v));
    return make_float2(__uint_as_float(lo), __uint_as_float(hi));
}

// ---------------- GEMM1: hs = (x @ W1) * dinv ---------------------------------
__global__ __launch_bounds__(128) void gemm1(const float* __restrict__ x,
                                             const float* __restrict__ W1, int N) {
    __shared__ ulonglong2 Ws[FIN * 4];   // 512 x 16 floats = 32KB
    const ulonglong2* Wg = (const ulonglong2*)W1;
    for (int i = threadIdx.x; i < FIN * 4; i += 128) Ws[i] = Wg[i];
    __syncthreads();

    int base = blockIdx.x * 512 + threadIdx.x * 4;
    if (base >= N) return;

    unsigned long long acc[4][8];
#pragma unroll
    for (int r = 0; r < 4; r++)
#pragma unroll
        for (int p = 0; p < 8; p++) acc[r][p] = 0ull;

    int row[4];
    const float* xp[4];
#pragma unroll
    for (int r = 0; r < 4; r++) {
        row[r] = min(base + r, N - 1);
        xp[r] = x + (size_t)row[r] * FIN;
    }

    for (int k = 0; k < FIN; k += 4) {
        float xv[4][4];
#pragma unroll
        for (int r = 0; r < 4; r++)
            *(float4*)xv[r] = *(const float4*)(xp[r] + k);
#pragma unroll
        for (int j = 0; j < 4; j++) {
            ulonglong2 wa = Ws[(k + j) * 4 + 0];
            ulonglong2 wb = Ws[(k + j) * 4 + 1];
            ulonglong2 wc = Ws[(k + j) * 4 + 2];
            ulonglong2 wd = Ws[(k + j) * 4 + 3];
#pragma unroll
            for (int r = 0; r < 4; r++) {
                unsigned long long px = pack2(xv[r][j]);
                acc[r][0] = ffma2(px, wa.x, acc[r][0]);
                acc[r][1] = ffma2(px, wa.y, acc[r][1]);
                acc[r][2] = ffma2(px, wb.x, acc[r][2]);
                acc[r][3] = ffma2(px, wb.y, acc[r][3]);
                acc[r][4] = ffma2(px, wc.x, acc[r][4]);
                acc[r][5] = ffma2(px, wc.y, acc[r][5]);
                acc[r][6] = ffma2(px, wd.x, acc[r][6]);
                acc[r][7] = ffma2(px, wd.y, acc[r][7]);
            }
        }
    }

#pragma unroll
    for (int r = 0; r < 4; r++) {
        if (base + r >= N) break;
        int rw = row[r];
        float dv = g_dinv[rw];
        float* hp = g_hs + (size_t)rw * HID;
#pragma unroll
        for (int p = 0; p < 8; p++) {
            float2 v = unpack2(acc[r][p]);
            hp[2 * p + 0] = v.x * dv;
            hp[2 * p + 1] = v.y * dv;
        }
    }
}

// ---------------- CSR aggregation (atomic-free) -------------------------------
// 4 threads per dst node, each owns a float4 slice. Coalesced 64B gathers.
// Layer 1: ys = relu(dinv*(self + sum) + b1) * dinv
__global__ __launch_bounds__(256) void agg1(const float* __restrict__ b1, int N) {
    int t = threadIdx.x;
    int d = blockIdx.x * 64 + (t >> 2);
    if (d >= N) return;
    int part = t & 3;

    float4 acc = *(const float4*)(g_hs + (size_t)d * HID + part * 4);   // self-loop
    int beg = g_row[d];
    int end = beg + g_deg[d];

    int e = beg;
    for (; e + 4 <= end; e += 4) {
        int s0 = g_csr[e], s1 = g_csr[e + 1], s2 = g_csr[e + 2], s3 = g_csr[e + 3];
        float4 v0 = *(const float4*)(g_hs + (size_t)s0 * HID + part * 4);
        float4 v1 = *(const float4*)(g_hs + (size_t)s1 * HID + part * 4);
        float4 v2 = *(const float4*)(g_hs + (size_t)s2 * HID + part * 4);
        float4 v3 = *(const float4*)(g_hs + (size_t)s3 * HID + part * 4);
        acc.x += v0.x + v1.x + v2.x + v3.x;
        acc.y += v0.y + v1.y + v2.y + v3.y;
        acc.z += v0.z + v1.z + v2.z + v3.z;
        acc.w += v0.w + v1.w + v2.w + v3.w;
    }
    for (; e < end; e++) {
        int s = g_csr[e];
        float4 v = *(const float4*)(g_hs + (size_t)s * HID + part * 4);
        acc.x += v.x; acc.y += v.y; acc.z += v.z; acc.w += v.w;
    }

    float dv = g_dinv[d];
    float4 bb = *(const float4*)(b1 + part * 4);
    float4 y;
    y.x = fmaxf(fmaf(acc.x, dv, bb.x), 0.0f) * dv;
    y.y = fmaxf(fmaf(acc.y, dv, bb.y), 0.0f) * dv;
    y.z = fmaxf(fmaf(acc.z, dv, bb.z), 0.0f) * dv;
    y.w = fmaxf(fmaf(acc.w, dv, bb.w), 0.0f) * dv;
    *(float4*)(g_ys + (size_t)d * HID + part * 4) = y;
}

// Layer 2: a2 = dinv*(self + sum)   (stored into g_hs, consumed by final_k)
__global__ __launch_bounds__(256) void agg2(int N) {
    int t = threadIdx.x;
    int d = blockIdx.x * 64 + (t >> 2);
    if (d >= N) return;
    int part = t & 3;

    float4 acc = *(const float4*)(g_ys + (size_t)d * HID + part * 4);   // self-loop
    int beg = g_row[d];
    int end = beg + g_deg[d];

    int e = beg;
    for (; e + 4 <= end; e += 4) {
        int s0 = g_csr[e], s1 = g_csr[e + 1], s2 = g_csr[e + 2], s3 = g_csr[e + 3];
        float4 v0 = *(const float4*)(g_ys + (size_t)s0 * HID + part * 4);
        float4 v1 = *(const float4*)(g_ys + (size_t)s1 * HID + part * 4);
        float4 v2 = *(const float4*)(g_ys + (size_t)s2 * HID + part * 4);
        float4 v3 = *(const float4*)(g_ys + (size_t)s3 * HID + part * 4);
        acc.x += v0.x + v1.x + v2.x + v3.x;
        acc.y += v0.y + v1.y + v2.y + v3.y;
        acc.z += v0.z + v1.z + v2.z + v3.z;
        acc.w += v0.w + v1.w + v2.w + v3.w;
    }
    for (; e < end; e++) {
        int s = g_csr[e];
        float4 v = *(const float4*)(g_ys + (size_t)s * HID + part * 4);
        acc.x += v.x; acc.y += v.y; acc.z += v.z; acc.w += v.w;
    }

    float dv = g_dinv[d];
    float4 a;
    a.x = acc.x * dv; a.y = acc.y * dv; a.z = acc.z * dv; a.w = acc.w * dv;
    *(float4*)(g_hs + (size_t)d * HID + part * 4) = a;
}

// ---------------- final: logits = a2@W2 + b2 ; log_softmax --------------------
__global__ __launch_bounds__(128) void final_k(const float* __restrict__ W2,
                                               const float* __restrict__ b2,
                                               float* __restrict__ out_lsm,
                                               float* __restrict__ out_logits,
                                               int N, int write_logits) {
    __shared__ float Ws[HID * NC];
    __shared__ float Bs[NC];
    for (int i = threadIdx.x; i < HID * NC; i += 128) Ws[i] = W2[i];
    if (threadIdx.x < NC) Bs[threadIdx.x] = b2[threadIdx.x];
    __syncthreads();

    int node = blockIdx.x * 128 + threadIdx.x;
    if (node >= N) return;

    const float* ap = g_hs + (size_t)node * HID;
    float a[HID];
#pragma unroll
    for (int j = 0; j < HID; j++) a[j] = ap[j];

    float z[NC];
#pragma unroll
    for (int c = 0; c < NC; c++) z[c] = Bs[c];
#pragma unroll
    for (int j = 0; j < HID; j++) {
        float aj = a[j];
#pragma unroll
        for (int c = 0; c < NC; c++) z[c] = fmaf(aj, Ws[j * NC + c], z[c]);
    }

    float m = z[0];
#pragma unroll
    for (int c = 1; c < NC; c++) m = fmaxf(m, z[c]);
    float s = 0.0f;
#pragma unroll
    for (int c = 0; c < NC; c++) s += __expf(z[c] - m);
    float lse = m + __logf(s);

    float* ol = out_lsm + (size_t)node * NC;
#pragma unroll
    for (int c = 0; c < NC; c++) ol[c] = z[c] - lse;
    if (write_logits) {
        float* og = out_logits + (size_t)node * NC;
#pragma unroll
        for (int c = 0; c < NC; c++) og[c] = z[c];
    }
}

// ---------------- launch ------------------------------------------------------
extern "C" void kernel_launch(void* const* d_in, const int* in_sizes, int n_in,
                              void* d_out, int out_size) {
    const float* x  = (const float*)d_in[0];
    const void*  ei = d_in[1];
    const float* W1 = (const float*)d_in[2];
    const float* b1 = (const float*)d_in[3];
    const float* W2 = (const float*)d_in[4];
    const float* b2 = (const float*)d_in[5];

    int E = in_sizes[1] / 2;
    if (E > MAXE) E = MAXE;
    int N = in_sizes[0] / FIN;
    if (N > NN) N = NN;

    float* out = (float*)d_out;
    int write_logits = (out_size >= 2 * N * NC) ? 1 : 0;
    float* out_lsm = out;
    float* out_logits = out + (size_t)N * NC;

    int nb_nodes = (N + 255) / 256;
    int nb_edges = (E + 255) / 256;
    int nb_scan  = (N + SCAN_B - 1) / SCAN_B;
    int nb_agg   = (N + 63) / 64;

    detect_idx<<<1, 256>>>((const unsigned int*)ei, E);
    zero_deg<<<nb_nodes, 256>>>(N);
    count_deg<<<nb_edges, 256>>>(ei, E);
    scan1<<<nb_scan, SCAN_B>>>(N);
    scan2<<<1, 256>>>(nb_scan);
    scan3<<<nb_scan, SCAN_B>>>(N);
    csr_fill<<<nb_edges, 256>>>(ei, E);
    gemm1<<<(N + 511) / 512, 128>>>(x, W1, N);
    agg1<<<nb_agg, 256>>>(b1, N);
    agg2<<<nb_agg, 256>>>(N);
    final_k<<<(N + 127) / 128, 128>>>(W2, b2, out_lsm, out_logits, N, write_logits);
}

// round 6
// speedup vs baseline: 1.9124x; 1.1749x over previous
#include <cuda_runtime.h>

#define NN  100000      // nodes
#define FIN 512         // input features
#define HID 16          // hidden
#define NC  40          // classes
#define MAXE 4000000    // capacity for edge scratch
#define SCAN_B 512      // elems per scan block

// ---------------- device scratch --------------------------------------------
__device__ int   g_is64;
__device__ int   g_deg [NN];
__device__ int   g_scan[NN];
__device__ int   g_row [NN];
__device__ int   g_cur [NN];
__device__ int   g_bsum[256];
__device__ int   g_bpre[256];
__device__ float g_dinv[NN];
__device__ int   g_csr[MAXE];
__device__ float g_h [(size_t)NN * HID];   // raw x@W1 (written on side stream)
__device__ float g_hs[(size_t)NN * HID];   // h1*dinv, later a2
__device__ float g_ys[(size_t)NN * HID];   // relu(out1)*dinv

// ---------------- init: zero deg + detect index dtype -------------------------
__global__ __launch_bounds__(256) void init_k(const unsigned int* __restrict__ w,
                                              int E, int N) {
    int i = blockIdx.x * 256 + threadIdx.x;
    if (i < N) g_deg[i] = 0;
    if (blockIdx.x == 0) {
        __shared__ unsigned int sh[256];
        unsigned int acc = 0;
        int n = min(E, 4096);
        for (int j = threadIdx.x; j < n; j += 256) acc |= w[2 * j + 1];
        sh[threadIdx.x] = acc;
        __syncthreads();
        for (int s = 128; s > 0; s >>= 1) {
            if (threadIdx.x < s) sh[threadIdx.x] |= sh[threadIdx.x + s];
            __syncthreads();
        }
        if (threadIdx.x == 0) g_is64 = (sh[0] == 0u) ? 1 : 0;
    }
}

// ---------------- degree count ------------------------------------------------
__global__ __launch_bounds__(256) void count_deg(const void* __restrict__ ei, int E) {
    int e = blockIdx.x * 256 + threadIdx.x;
    if (e >= E) return;
    int d;
    if (g_is64) {
        const long long* p = (const long long*)ei;
        d = (int)p[e + E];
    } else {
        const int* p = (const int*)ei;
        d = p[e + E];
    }
    atomicAdd(&g_deg[d], 1);
}

// ---------------- prefix scan (3 kernels) -------------------------------------
__global__ __launch_bounds__(SCAN_B) void scan1(int N) {
    __shared__ int sh[SCAN_B];
    int gid = blockIdx.x * SCAN_B + threadIdx.x;
    int v = (gid < N) ? g_deg[gid] : 0;
    sh[threadIdx.x] = v;
    __syncthreads();
    for (int off = 1; off < SCAN_B; off <<= 1) {
        int t = (threadIdx.x >= off) ? sh[threadIdx.x - off] : 0;
        __syncthreads();
        sh[threadIdx.x] += t;
        __syncthreads();
    }
    if (gid < N) g_scan[gid] = sh[threadIdx.x];
    if (threadIdx.x == SCAN_B - 1) g_bsum[blockIdx.x] = sh[SCAN_B - 1];
}
__global__ __launch_bounds__(256) void scan2(int nblk) {
    __shared__ int sh[256];
    int v = (threadIdx.x < nblk) ? g_bsum[threadIdx.x] : 0;
    sh[threadIdx.x] = v;
    __syncthreads();
    for (int off = 1; off < 256; off <<= 1) {
        int t = (threadIdx.x >= off) ? sh[threadIdx.x - off] : 0;
        __syncthreads();
        sh[threadIdx.x] += t;
        __syncthreads();
    }
    g_bpre[threadIdx.x] = sh[threadIdx.x] - v;   // exclusive
}
__global__ __launch_bounds__(SCAN_B) void scan3(int N) {
    int gid = blockIdx.x * SCAN_B + threadIdx.x;
    if (gid >= N) return;
    int dg = g_deg[gid];
    int rs = g_scan[gid] - dg + g_bpre[blockIdx.x];
    g_row[gid] = rs;
    g_cur[gid] = rs;
    g_dinv[gid] = rsqrtf((float)(dg + 1));   // +1 self-loop
}

// ---------------- CSR fill ----------------------------------------------------
__global__ __launch_bounds__(256) void csr_fill(const void* __restrict__ ei, int E) {
    int e = blockIdx.x * 256 + threadIdx.x;
    if (e >= E) return;
    int s, d;
    if (g_is64) {
        const long long* p = (const long long*)ei;
        s = (int)p[e];
        d = (int)p[e + E];
    } else {
        const int* p = (const int*)ei;
        s = p[e];
        d = p[e + E];
    }
    int pos = atomicAdd(&g_cur[d], 1);
    g_csr[pos] = s;
}

// ---------------- packed f32x2 helpers ----------------------------------------
__device__ __forceinline__ unsigned long long pack2(float v) {
    unsigned long long r;
    unsigned int u = __float_as_uint(v);
    asm("mov.b64 %0, {%1, %1};" : "=l"(r) : "r"(u));
    return r;
}
__device__ __forceinline__ unsigned long long ffma2(unsigned long long a,
                                                    unsigned long long b,
                                                    unsigned long long c) {
    unsigned long long d;
    asm("fma.rn.f32x2 %0, %1, %2, %3;" : "=l"(d) : "l"(a), "l"(b), "l"(c));
    return d;
}
__device__ __forceinline__ float2 unpack2(unsigned long long v) {
    unsigned int lo, hi;
    asm("mov.b64 {%0, %1}, %2;" : "=r"(lo), "=r"(hi) : "l"(v));
    return make_float2(__uint_as_float(lo), __uint_as_float(hi));
}

// ---------------- GEMM1 (raw): h = x @ W1  (no dinv; runs on side stream) -----
__global__ __launch_bounds__(128) void gemm1(const float* __restrict__ x,
                                             const float* __restrict__ W1, int N) {
    __shared__ ulonglong2 Ws[FIN * 4];   // 512 x 16 floats = 32KB
    const ulonglong2* Wg = (const ulonglong2*)W1;
    for (int i = threadIdx.x; i < FIN * 4; i += 128) Ws[i] = Wg[i];
    __syncthreads();

    int base = blockIdx.x * 512 + threadIdx.x * 4;
    if (base >= N) return;

    unsigned long long acc[4][8];
#pragma unroll
    for (int r = 0; r < 4; r++)
#pragma unroll
        for (int p = 0; p < 8; p++) acc[r][p] = 0ull;

    int row[4];
    const float* xp[4];
#pragma unroll
    for (int r = 0; r < 4; r++) {
        row[r] = min(base + r, N - 1);
        xp[r] = x + (size_t)row[r] * FIN;
    }

    for (int k = 0; k < FIN; k += 4) {
        float xv[4][4];
#pragma unroll
        for (int r = 0; r < 4; r++)
            *(float4*)xv[r] = *(const float4*)(xp[r] + k);
#pragma unroll
        for (int j = 0; j < 4; j++) {
            ulonglong2 wa = Ws[(k + j) * 4 + 0];
            ulonglong2 wb = Ws[(k + j) * 4 + 1];
            ulonglong2 wc = Ws[(k + j) * 4 + 2];
            ulonglong2 wd = Ws[(k + j) * 4 + 3];
#pragma unroll
            for (int r = 0; r < 4; r++) {
                unsigned long long px = pack2(xv[r][j]);
                acc[r][0] = ffma2(px, wa.x, acc[r][0]);
                acc[r][1] = ffma2(px, wa.y, acc[r][1]);
                acc[r][2] = ffma2(px, wb.x, acc[r][2]);
                acc[r][3] = ffma2(px, wb.y, acc[r][3]);
                acc[r][4] = ffma2(px, wc.x, acc[r][4]);
                acc[r][5] = ffma2(px, wc.y, acc[r][5]);
                acc[r][6] = ffma2(px, wd.x, acc[r][6]);
                acc[r][7] = ffma2(px, wd.y, acc[r][7]);
            }
        }
    }

#pragma unroll
    for (int r = 0; r < 4; r++) {
        if (base + r >= N) break;
        int rw = row[r];
        float* hp = g_h + (size_t)rw * HID;
#pragma unroll
        for (int p = 0; p < 8; p++) {
            float2 v = unpack2(acc[r][p]);
            hp[2 * p + 0] = v.x;
            hp[2 * p + 1] = v.y;
        }
    }
}

// ---------------- scale: hs = h * dinv (after join) ---------------------------
__global__ __launch_bounds__(256) void scale_h(int N) {
    int i = blockIdx.x * 256 + threadIdx.x;
    if (i >= N) return;
    float dv = g_dinv[i];
    const float4* hp = (const float4*)(g_h + (size_t)i * HID);
    float4* op = (float4*)(g_hs + (size_t)i * HID);
#pragma unroll
    for (int p = 0; p < 4; p++) {
        float4 v = hp[p];
        v.x *= dv; v.y *= dv; v.z *= dv; v.w *= dv;
        op[p] = v;
    }
}

// ---------------- CSR aggregation (atomic-free, unroll 8) ---------------------
// 4 threads per dst node, each owns a float4 slice. Coalesced 64B gathers.
// Layer 1: ys = relu(dinv*(self + sum) + b1) * dinv
__global__ __launch_bounds__(256) void agg1(const float* __restrict__ b1, int N) {
    int t = threadIdx.x;
    int d = blockIdx.x * 64 + (t >> 2);
    if (d >= N) return;
    int part = t & 3;
    const float* tbl = g_hs + part * 4;

    float4 acc = *(const float4*)(tbl + (size_t)d * HID);   // self-loop
    int beg = g_row[d];
    int deg = g_deg[d];
    int end = beg + deg;

    int e = beg;
    int end8 = beg + (deg & ~7);
    for (; e < end8; e += 8) {
        int s0 = g_csr[e],     s1 = g_csr[e + 1], s2 = g_csr[e + 2], s3 = g_csr[e + 3];
        int s4 = g_csr[e + 4], s5 = g_csr[e + 5], s6 = g_csr[e + 6], s7 = g_csr[e + 7];
        float4 v0 = *(const float4*)(tbl + (size_t)s0 * HID);
        float4 v1 = *(const float4*)(tbl + (size_t)s1 * HID);
        float4 v2 = *(const float4*)(tbl + (size_t)s2 * HID);
        float4 v3 = *(const float4*)(tbl + (size_t)s3 * HID);
        float4 v4 = *(const float4*)(tbl + (size_t)s4 * HID);
        float4 v5 = *(const float4*)(tbl + (size_t)s5 * HID);
        float4 v6 = *(const float4*)(tbl + (size_t)s6 * HID);
        float4 v7 = *(const float4*)(tbl + (size_t)s7 * HID);
        acc.x += (v0.x + v1.x) + (v2.x + v3.x) + (v4.x + v5.x) + (v6.x + v7.x);
        acc.y += (v0.y + v1.y) + (v2.y + v3.y) + (v4.y + v5.y) + (v6.y + v7.y);
        acc.z += (v0.z + v1.z) + (v2.z + v3.z) + (v4.z + v5.z) + (v6.z + v7.z);
        acc.w += (v0.w + v1.w) + (v2.w + v3.w) + (v4.w + v5.w) + (v6.w + v7.w);
    }
    for (; e < end; e++) {
        int s = g_csr[e];
        float4 v = *(const float4*)(tbl + (size_t)s * HID);
        acc.x += v.x; acc.y += v.y; acc.z += v.z; acc.w += v.w;
    }

    float dv = g_dinv[d];
    float4 bb = *(const float4*)(b1 + part * 4);
    float4 y;
    y.x = fmaxf(fmaf(acc.x, dv, bb.x), 0.0f) * dv;
    y.y = fmaxf(fmaf(acc.y, dv, bb.y), 0.0f) * dv;
    y.z = fmaxf(fmaf(acc.z, dv, bb.z), 0.0f) * dv;
    y.w = fmaxf(fmaf(acc.w, dv, bb.w), 0.0f) * dv;
    *(float4*)(g_ys + (size_t)d * HID + part * 4) = y;
}

// Layer 2: a2 = dinv*(self + sum)   (stored into g_hs, consumed by final_k)
__global__ __launch_bounds__(256) void agg2(int N) {
    int t = threadIdx.x;
    int d = blockIdx.x * 64 + (t >> 2);
    if (d >= N) return;
    int part = t & 3;
    const float* tbl = g_ys + part * 4;

    float4 acc = *(const float4*)(tbl + (size_t)d * HID);   // self-loop
    int beg = g_row[d];
    int deg = g_deg[d];
    int end = beg + deg;

    int e = beg;
    int end8 = beg + (deg & ~7);
    for (; e < end8; e += 8) {
        int s0 = g_csr[e],     s1 = g_csr[e + 1], s2 = g_csr[e + 2], s3 = g_csr[e + 3];
        int s4 = g_csr[e + 4], s5 = g_csr[e + 5], s6 = g_csr[e + 6], s7 = g_csr[e + 7];
        float4 v0 = *(const float4*)(tbl + (size_t)s0 * HID);
        float4 v1 = *(const float4*)(tbl + (size_t)s1 * HID);
        float4 v2 = *(const float4*)(tbl + (size_t)s2 * HID);
        float4 v3 = *(const float4*)(tbl + (size_t)s3 * HID);
        float4 v4 = *(const float4*)(tbl + (size_t)s4 * HID);
        float4 v5 = *(const float4*)(tbl + (size_t)s5 * HID);
        float4 v6 = *(const float4*)(tbl + (size_t)s6 * HID);
        float4 v7 = *(const float4*)(tbl + (size_t)s7 * HID);
        acc.x += (v0.x + v1.x) + (v2.x + v3.x) + (v4.x + v5.x) + (v6.x + v7.x);
        acc.y += (v0.y + v1.y) + (v2.y + v3.y) + (v4.y + v5.y) + (v6.y + v7.y);
        acc.z += (v0.z + v1.z) + (v2.z + v3.z) + (v4.z + v5.z) + (v6.z + v7.z);
        acc.w += (v0.w + v1.w) + (v2.w + v3.w) + (v4.w + v5.w) + (v6.w + v7.w);
    }
    for (; e < end; e++) {
        int s = g_csr[e];
        float4 v = *(const float4*)(tbl + (size_t)s * HID);
        acc.x += v.x; acc.y += v.y; acc.z += v.z; acc.w += v.w;
    }

    float dv = g_dinv[d];
    float4 a;
    a.x = acc.x * dv; a.y = acc.y * dv; a.z = acc.z * dv; a.w = acc.w * dv;
    *(float4*)(g_hs + (size_t)d * HID + part * 4) = a;
}

// ---------------- final: logits = a2@W2 + b2 ; log_softmax --------------------
__global__ __launch_bounds__(128) void final_k(const float* __restrict__ W2,
                                               const float* __restrict__ b2,
                                               float* __restrict__ out_lsm,
                                               float* __restrict__ out_logits,
                                               int N, int write_logits) {
    __shared__ float Ws[HID * NC];
    __shared__ float Bs[NC];
    for (int i = threadIdx.x; i < HID * NC; i += 128) Ws[i] = W2[i];
    if (threadIdx.x < NC) Bs[threadIdx.x] = b2[threadIdx.x];
    __syncthreads();

    int node = blockIdx.x * 128 + threadIdx.x;
    if (node >= N) return;

    const float* ap = g_hs + (size_t)node * HID;
    float a[HID];
#pragma unroll
    for (int j = 0; j < HID; j++) a[j] = ap[j];

    float z[NC];
#pragma unroll
    for (int c = 0; c < NC; c++) z[c] = Bs[c];
#pragma unroll
    for (int j = 0; j < HID; j++) {
        float aj = a[j];
#pragma unroll
        for (int c = 0; c < NC; c++) z[c] = fmaf(aj, Ws[j * NC + c], z[c]);
    }

    float m = z[0];
#pragma unroll
    for (int c = 1; c < NC; c++) m = fmaxf(m, z[c]);
    float s = 0.0f;
#pragma unroll
    for (int c = 0; c < NC; c++) s += __expf(z[c] - m);
    float lse = m + __logf(s);

    float* ol = out_lsm + (size_t)node * NC;
#pragma unroll
    for (int c = 0; c < NC; c++) ol[c] = z[c] - lse;
    if (write_logits) {
        float* og = out_logits + (size_t)node * NC;
#pragma unroll
        for (int c = 0; c < NC; c++) og[c] = z[c];
    }
}

// ---------------- launch ------------------------------------------------------
extern "C" void kernel_launch(void* const* d_in, const int* in_sizes, int n_in,
                              void* d_out, int out_size) {
    const float* x  = (const float*)d_in[0];
    const void*  ei = d_in[1];
    const float* W1 = (const float*)d_in[2];
    const float* b1 = (const float*)d_in[3];
    const float* W2 = (const float*)d_in[4];
    const float* b2 = (const float*)d_in[5];

    int E = in_sizes[1] / 2;
    if (E > MAXE) E = MAXE;
    int N = in_sizes[0] / FIN;
    if (N > NN) N = NN;

    float* out = (float*)d_out;
    int write_logits = (out_size >= 2 * N * NC) ? 1 : 0;
    float* out_lsm = out;
    float* out_logits = out + (size_t)N * NC;

    int nb_nodes = (N + 255) / 256;
    int nb_edges = (E + 255) / 256;
    int nb_scan  = (N + SCAN_B - 1) / SCAN_B;
    int nb_agg   = (N + 63) / 64;

    // lazy side-stream setup (created on the uncaptured correctness call)
    static cudaStream_t s2 = 0;
    static cudaEvent_t evF = 0, evJ = 0;
    static int inited = 0;
    if (!inited) {
        if (cudaStreamCreateWithFlags(&s2, cudaStreamNonBlocking) != cudaSuccess) s2 = 0;
        if (s2) {
            if (cudaEventCreateWithFlags(&evF, cudaEventDisableTiming) != cudaSuccess ||
                cudaEventCreateWithFlags(&evJ, cudaEventDisableTiming) != cudaSuccess) {
                s2 = 0;
            }
        }
        inited = 1;
    }
    int fork = (s2 != 0);

    // branch B: dense projection (independent of edge pipeline)
    if (fork) {
        cudaEventRecord(evF, 0);
        cudaStreamWaitEvent(s2, evF, 0);
        gemm1<<<(N + 511) / 512, 128, 0, s2>>>(x, W1, N);
        cudaEventRecord(evJ, s2);
    } else {
        gemm1<<<(N + 511) / 512, 128>>>(x, W1, N);
    }

    // branch A: edge pipeline (default stream)
    init_k<<<nb_nodes, 256>>>((const unsigned int*)ei, E, N);
    count_deg<<<nb_edges, 256>>>(ei, E);
    scan1<<<nb_scan, SCAN_B>>>(N);
    scan2<<<1, 256>>>(nb_scan);
    scan3<<<nb_scan, SCAN_B>>>(N);
    csr_fill<<<nb_edges, 256>>>(ei, E);

    // join
    if (fork) cudaStreamWaitEvent(0, evJ, 0);
    scale_h<<<nb_nodes, 256>>>(N);
    agg1<<<nb_agg, 256>>>(b1, N);
    agg2<<<nb_agg, 256>>>(N);
    final_k<<<(N + 127) / 128, 128>>>(W2, b2, out_lsm, out_logits, N, write_logits);
}